// round 1
// baseline (speedup 1.0000x reference)
#include <cuda_runtime.h>
#include <math.h>

#define NIMG 8
#define CCH  3
#define HI_  512
#define WI_  512
#define HO_  2048
#define WO_  2048

// per-layer affine params: a, tx, b, ty
__device__ float g_prm[NIMG][4];

__global__ void prep_kernel(const float* __restrict__ coor) {
    int n = threadIdx.x;
    if (n < NIMG) {
        float c0 = coor[n * 4 + 0];
        float c1 = coor[n * 4 + 1];
        float c2 = coor[n * 4 + 2];
        float c3 = coor[n * 4 + 3];
        float X  = (1.0f / (1.0f + expf(-c0))) * (float)WO_;
        float Y  = (1.0f / (1.0f + expf(-c1))) * (float)HO_;
        float Wb = (1.0f / (1.0f + expf(-c2))) * (float)WO_;
        float Hb = (1.0f / (1.0f + expf(-c3))) * (float)HO_;
        float a  = (float)WO_ / (Wb + 1e-8f);
        float tx = 2.0f / (float)WO_ * ((float)WO_ * 0.5f - X) * a;
        float b  = (float)HO_ / (Hb + 1e-8f);
        float ty = 2.0f / (float)HO_ * ((float)HO_ * 0.5f - Y) * b;
        g_prm[n][0] = a;
        g_prm[n][1] = tx;
        g_prm[n][2] = b;
        g_prm[n][3] = ty;
    }
}

// One thread handles 4 consecutive output pixels (float4 bg/out), all 3 channels,
// looping the 8 layers in compositing order with a register accumulator.
__global__ __launch_bounds__(256) void composite_kernel(
    const float* __restrict__ src,   // [8,3,512,512]
    const float* __restrict__ bg,    // [1,3,2048,2048]
    float* __restrict__ out)         // [1,3,2048,2048]
{
    int tid = blockIdx.x * blockDim.x + threadIdx.x;   // 1048576 threads exactly
    int y   = tid >> 9;                                // 512 float4 groups per row
    int x0  = (tid & 511) << 2;

    const int plane4 = (HO_ * WO_) >> 2;               // float4s per channel plane
    int base4 = y * (WO_ >> 2) + (x0 >> 2);

    const float4* bg4  = (const float4*)bg;
    float4*       out4 = (float4*)out;

    float4 b0 = bg4[base4];
    float4 b1 = bg4[base4 + plane4];
    float4 b2 = bg4[base4 + 2 * plane4];

    float acc[3][4] = {
        {b0.x, b0.y, b0.z, b0.w},
        {b1.x, b1.y, b1.z, b1.w},
        {b2.x, b2.y, b2.z, b2.w},
    };

    // snapshot layer params into registers
    float prm[NIMG][4];
#pragma unroll
    for (int n = 0; n < NIMG; ++n) {
#pragma unroll
        for (int k = 0; k < 4; ++k) prm[n][k] = g_prm[n][k];
    }

    float ysn = (2.0f * (float)y + 1.0f) / (float)HO_ - 1.0f;

    // x base coords (normalized) for the 4 pixels
    float xsn[4];
#pragma unroll
    for (int j = 0; j < 4; ++j)
        xsn[j] = (2.0f * (float)(x0 + j) + 1.0f) / (float)WO_ - 1.0f;

#pragma unroll
    for (int n = 0; n < NIMG; ++n) {
        float a  = prm[n][0];
        float tx = prm[n][1];
        float b  = prm[n][2];
        float ty = prm[n][3];

        // y (row) terms — shared by the 4 pixels
        float gy  = b * ysn + ty;
        float iy  = ((gy + 1.0f) * (float)HI_ - 1.0f) * 0.5f;
        float y0f = floorf(iy);
        float wy1 = iy - y0f;
        float wy0 = 1.0f - wy1;
        int   yi0 = (int)y0f;
        int   yi1 = yi0 + 1;
        float vy0 = (yi0 >= 0 && yi0 < HI_) ? 1.0f : 0.0f;
        float vy1 = (yi1 >= 0 && yi1 < HI_) ? 1.0f : 0.0f;
        float wyv0 = wy0 * vy0;
        float wyv1 = wy1 * vy1;
        float sumwy = wyv0 + wyv1;
        if (sumwy == 0.0f) continue;    // entire row out of this layer's box

        int y0c = min(max(yi0, 0), HI_ - 1);
        int y1c = min(max(yi1, 0), HI_ - 1);
        const float* s0  = src + (size_t)n * (CCH * HI_ * WI_);
        int row0 = y0c * WI_;
        int row1 = y1c * WI_;

#pragma unroll
        for (int j = 0; j < 4; ++j) {
            float gx  = a * xsn[j] + tx;
            float ix  = ((gx + 1.0f) * (float)WI_ - 1.0f) * 0.5f;
            float x0f = floorf(ix);
            float wx1 = ix - x0f;
            float wx0 = 1.0f - wx1;
            int   xi0 = (int)x0f;
            int   xi1 = xi0 + 1;
            float vx0 = (xi0 >= 0 && xi0 < WI_) ? 1.0f : 0.0f;
            float vx1 = (xi1 >= 0 && xi1 < WI_) ? 1.0f : 0.0f;
            float wxv0 = wx0 * vx0;
            float wxv1 = wx1 * vx1;
            float sumwx = wxv0 + wxv1;
            float m = sumwy * sumwx;
            if (m == 0.0f) continue;

            int x0c = min(max(xi0, 0), WI_ - 1);
            int x1c = min(max(xi1, 0), WI_ - 1);
            float om = 1.0f - m;

#pragma unroll
            for (int c = 0; c < CCH; ++c) {
                const float* sp = s0 + c * (HI_ * WI_);
                float v00 = __ldg(sp + row0 + x0c);
                float v10 = __ldg(sp + row1 + x0c);
                float v01 = __ldg(sp + row0 + x1c);
                float v11 = __ldg(sp + row1 + x1c);
                float r0 = v00 * wyv0 + v10 * wyv1;
                float r1 = v01 * wyv0 + v11 * wyv1;
                float samp = r0 * wxv0 + r1 * wxv1;
                acc[c][j] = acc[c][j] * om + samp * m;
            }
        }
    }

    out4[base4]              = make_float4(acc[0][0], acc[0][1], acc[0][2], acc[0][3]);
    out4[base4 + plane4]     = make_float4(acc[1][0], acc[1][1], acc[1][2], acc[1][3]);
    out4[base4 + 2 * plane4] = make_float4(acc[2][0], acc[2][1], acc[2][2], acc[2][3]);
}

extern "C" void kernel_launch(void* const* d_in, const int* in_sizes, int n_in,
                              void* d_out, int out_size) {
    const float* src  = (const float*)d_in[0];   // src_img [8,3,512,512]
    const float* bg   = (const float*)d_in[1];   // bg_img  [1,3,2048,2048]
    const float* coor = (const float*)d_in[2];   // coor    [8,4]
    float*       out  = (float*)d_out;           // [1,3,2048,2048]

    prep_kernel<<<1, 32>>>(coor);

    const int threads = 256;
    const int total   = (HO_ * WO_) / 4;         // one thread per 4 pixels
    composite_kernel<<<total / threads, threads>>>(src, bg, out);
}